// round 1
// baseline (speedup 1.0000x reference)
#include <cuda_runtime.h>
#include <math.h>

#define NTOT 4992
#define BB 128
#define HN 39
#define WN 39
#define POS 1521      // 39*39
#define E0 200064     // B*E_PER
#define ET 205056     // E0 + NTOT self loops
#define HEADS 8
#define HID 64
#define OUTC 64
#define F1 78
#define D1 512

// ---------------- scratch (static device memory; no allocation) ----------------
__device__ float d_x1[BB*8*POS];      // conv1 output (B,8,39,39)
__device__ float d_gi[BB*POS*3];      // GRU input gates (b,t,w,3)
__device__ float d_xn[NTOT*F1];       // node features (N,78)
__device__ float d_xl1[NTOT*D1];
__device__ float d_xr1[NTOT*D1];
__device__ float d_h1[NTOT*D1];
__device__ float d_xl2[NTOT*OUTC];
__device__ float d_xr2[NTOT*OUTC];
__device__ int   d_deg[NTOT];
__device__ int   d_off[NTOT+1];
__device__ int   d_cur[NTOT];
__device__ int   d_csr[ET];

__device__ __forceinline__ float nz(float v){ return isnan(v) ? 0.0f : v; }

// ---------------- init ----------------
__global__ void k_init(){
    int i = blockIdx.x*blockDim.x + threadIdx.x;
    if (i < NTOT) d_deg[i] = 0;
}

// ---------------- conv1 (1x1, 3->8) + BN + ReLU ----------------
__global__ void k_conv1(const float* __restrict__ man, const float* __restrict__ ac,
                        const float* __restrict__ ve,
                        const float* __restrict__ w1, const float* __restrict__ b1,
                        const float* __restrict__ g1, const float* __restrict__ bb1){
    int idx = blockIdx.x*blockDim.x + threadIdx.x;
    if (idx >= BB*POS) return;
    int b = idx / POS, p = idx % POS;
    float c0 = nz(man[idx]), c1 = nz(ac[idx]), c2 = nz(ve[idx]);
    const float inv = rsqrtf(1.0f + 1e-5f);
    #pragma unroll
    for (int o=0;o<8;o++){
        float v = w1[o*3+0]*c0 + w1[o*3+1]*c1 + w1[o*3+2]*c2 + b1[o];
        v = v * (g1[o]*inv) + bb1[o];
        d_x1[(b*8+o)*POS + p] = fmaxf(v, 0.0f);
    }
}

// ---------------- conv2 (3x3 pad1, 8->16) + BN + GRU input projection (16->3) ----------------
__global__ void k_conv2(const float* __restrict__ w2, const float* __restrict__ b2,
                        const float* __restrict__ g2, const float* __restrict__ bb2,
                        const float* __restrict__ wih, const float* __restrict__ bih){
    __shared__ float sw2[1152];
    __shared__ float ssc[16], sof[16];
    __shared__ float swih[48];
    int tid = threadIdx.x;
    for (int i=tid;i<1152;i+=blockDim.x) sw2[i]=w2[i];
    if (tid<16){ float s = g2[tid]*rsqrtf(1.0f+1e-5f); ssc[tid]=s; sof[tid]=b2[tid]*s + bb2[tid]; }
    if (tid<48) swih[tid]=wih[tid];
    __syncthreads();
    int b = blockIdx.x;
    int p = blockIdx.y*blockDim.x + tid;
    if (p >= POS) return;
    int i = p / WN, j = p % WN;
    float acc[16];
    #pragma unroll
    for (int o=0;o<16;o++) acc[o]=0.f;
    const float* x1b = d_x1 + b*8*POS;
    for (int c=0;c<8;c++){
        #pragma unroll
        for (int di=0;di<3;di++){
            int ii = i+di-1; if (ii<0||ii>=HN) continue;
            #pragma unroll
            for (int dj=0;dj<3;dj++){
                int jj = j+dj-1; if (jj<0||jj>=WN) continue;
                float v = x1b[c*POS + ii*WN + jj];
                #pragma unroll
                for (int o=0;o<16;o++) acc[o] += sw2[o*72 + c*9 + di*3 + dj]*v;
            }
        }
    }
    float q0=bih[0], q1=bih[1], q2=bih[2];
    #pragma unroll
    for (int o=0;o<16;o++){
        float x2 = acc[o]*ssc[o] + sof[o];
        q0 += swih[0*16+o]*x2;
        q1 += swih[1*16+o]*x2;
        q2 += swih[2*16+o]*x2;
    }
    int base = (b*POS + p)*3;
    d_gi[base+0]=q0; d_gi[base+1]=q1; d_gi[base+2]=q2;
}

// ---------------- GRU over rows + masked feature assembly -> xn (N,78) ----------------
__global__ void k_gru(const float* __restrict__ man, const float* __restrict__ maskv,
                      const float* __restrict__ whh, const float* __restrict__ bhh){
    int node = blockIdx.x*blockDim.x + threadIdx.x;
    if (node >= NTOT) return;
    int b = node / WN, w = node % WN;
    float mk = maskv[node];                 // mask_view (B,39,1) flat
    float* xnr = d_xn + node*F1;
    for (int f=0; f<HN; f++) xnr[f] = nz(man[(b*HN+f)*WN + w]) * mk;
    float w0=whh[0], w1=whh[1], w2=whh[2];
    float bh0=bhh[0], bh1=bhh[1], bh2=bhh[2];
    float h = 0.f;
    for (int t=0;t<HN;t++){
        int base = (b*POS + t*WN + w)*3;
        float gi0=d_gi[base], gi1=d_gi[base+1], gi2=d_gi[base+2];
        float r = 1.f/(1.f+__expf(-(gi0 + w0*h + bh0)));
        float z = 1.f/(1.f+__expf(-(gi1 + w1*h + bh1)));
        float n = tanhf(gi2 + r*(w2*h + bh2));
        h = (1.f-z)*n + z*h;
        xnr[HN+t] = h*mk;
    }
}

// ---------------- CSR build (group edges by dst) ----------------
__global__ void k_hist(const int* __restrict__ eib){
    int e = blockIdx.x*blockDim.x + threadIdx.x;
    if (e >= ET) return;
    int dst = (e < E0) ? eib[E0 + e] : (e - E0);
    atomicAdd(&d_deg[dst], 1);
}

__global__ void k_scan(){      // single block, 1024 threads, chunk=5
    __shared__ int s[1024];
    int t = threadIdx.x;
    int loc[5]; int sum=0;
    #pragma unroll
    for (int k=0;k<5;k++){
        int i=t*5+k;
        int v = (i<NTOT)? d_deg[i]:0;
        loc[k]=sum; sum+=v;
    }
    s[t]=sum; __syncthreads();
    for (int dd=1; dd<1024; dd<<=1){
        int v = (t>=dd) ? s[t-dd] : 0;
        __syncthreads();
        s[t]+=v;
        __syncthreads();
    }
    int base = (t==0)?0 : s[t-1];
    #pragma unroll
    for (int k=0;k<5;k++){
        int i=t*5+k;
        if (i<NTOT){ int v = base+loc[k]; d_off[i]=v; d_cur[i]=v; }
    }
    if (t==1023) d_off[NTOT] = s[1023];
}

__global__ void k_scatter(const int* __restrict__ eib){
    int e = blockIdx.x*blockDim.x + threadIdx.x;
    if (e >= ET) return;
    int src, dst;
    if (e < E0){ src = eib[e]; dst = eib[E0+e]; }
    else { src = dst = e - E0; }
    int pos = atomicAdd(&d_cur[dst], 1);
    d_csr[pos] = src;
}

// ---------------- GEMM: C[n,m] = A[n,:] . W[m,:] + bias[m]  (64x64 tile, 256 thr) ----------------
// sel: 0 -> A=d_xn, C=d_xl1 ; 1 -> A=d_xn, C=d_xr1 ; 2 -> A=d_h1, C=d_xl2 ; 3 -> A=d_h1, C=d_xr2
__global__ void k_gemm(int sel, const float* __restrict__ W,
                       const float* __restrict__ bias, int M, int K){
    const float* A; float* C;
    if (sel==0){ A=d_xn; C=d_xl1; }
    else if (sel==1){ A=d_xn; C=d_xr1; }
    else if (sel==2){ A=d_h1; C=d_xl2; }
    else { A=d_h1; C=d_xr2; }

    __shared__ float As[64][17];
    __shared__ float Ws[64][17];
    int tid = threadIdx.x;
    int tx = tid & 15, ty = tid >> 4;
    int n0 = blockIdx.y*64, m0 = blockIdx.x*64;
    float acc[4][4] = {};
    for (int k0=0;k0<K;k0+=16){
        #pragma unroll
        for (int q=0;q<4;q++){
            int l = tid + q*256;
            int row = l >> 4, col = l & 15;
            As[row][col] = (k0+col < K) ? A[(n0+row)*K + k0+col] : 0.f;
            Ws[row][col] = (k0+col < K) ? W[(m0+row)*K + k0+col] : 0.f;
        }
        __syncthreads();
        #pragma unroll
        for (int kk=0;kk<16;kk++){
            float av[4], wv[4];
            #pragma unroll
            for (int i=0;i<4;i++) av[i] = As[ty*4+i][kk];
            #pragma unroll
            for (int j=0;j<4;j++) wv[j] = Ws[tx*4+j][kk];
            #pragma unroll
            for (int i=0;i<4;i++)
                #pragma unroll
                for (int j=0;j<4;j++) acc[i][j] += av[i]*wv[j];
        }
        __syncthreads();
    }
    #pragma unroll
    for (int i=0;i<4;i++){
        int n = n0 + ty*4 + i;
        #pragma unroll
        for (int j=0;j<4;j++){
            int mcol = m0 + tx*4 + j;
            C[n*M + mcol] = acc[i][j] + bias[mcol];
        }
    }
}

// ---------------- GAT1 aggregation: one-pass online softmax, warp per (dst,head) ----------------
__global__ void k_gat1(const float* __restrict__ att, const float* __restrict__ bias){
    int d = blockIdx.x;
    int h = threadIdx.x >> 5, lane = threadIdx.x & 31;
    int c0 = h*HID + lane, c1 = c0 + 32;
    float xr0 = d_xr1[d*D1 + c0], xr1v = d_xr1[d*D1 + c1];
    float a0 = att[c0], a1 = att[c1];
    float m = -INFINITY, den = 0.f, s0 = 0.f, s1 = 0.f;
    int eb = d_off[d], ee = d_off[d+1];
    for (int e=eb; e<ee; e++){
        int s = d_csr[e];
        float l0 = d_xl1[s*D1 + c0], l1 = d_xl1[s*D1 + c1];
        float t0 = l0 + xr0; t0 = t0>0.f? t0 : 0.2f*t0;
        float t1 = l1 + xr1v; t1 = t1>0.f? t1 : 0.2f*t1;
        float p = t0*a0 + t1*a1;
        #pragma unroll
        for (int o=16;o;o>>=1) p += __shfl_xor_sync(0xffffffffu, p, o);
        float mn = fmaxf(m, p);
        float sc = __expf(m - mn);
        float wv = __expf(p - mn);
        den = den*sc + wv;
        s0 = s0*sc + wv*l0;
        s1 = s1*sc + wv*l1;
        m = mn;
    }
    float inv = 1.f/den;
    float o0 = s0*inv + bias[c0];
    float o1 = s1*inv + bias[c1];
    d_h1[d*D1 + c0] = o0>0.f? o0 : (__expf(o0)-1.f);   // ELU
    d_h1[d*D1 + c1] = o1>0.f? o1 : (__expf(o1)-1.f);
}

// ---------------- GAT2 aggregation: warp per dst (1 head, 64 ch) ----------------
__global__ void k_gat2(const float* __restrict__ att, const float* __restrict__ bias,
                       float* __restrict__ out){
    int d = blockIdx.x*8 + (threadIdx.x>>5);
    int lane = threadIdx.x & 31;
    if (d >= NTOT) return;
    int c0 = lane, c1 = lane+32;
    float xr0 = d_xr2[d*OUTC + c0], xr1v = d_xr2[d*OUTC + c1];
    float a0 = att[c0], a1 = att[c1];
    float m = -INFINITY, den = 0.f, s0 = 0.f, s1 = 0.f;
    int eb = d_off[d], ee = d_off[d+1];
    for (int e=eb; e<ee; e++){
        int s = d_csr[e];
        float l0 = d_xl2[s*OUTC + c0], l1 = d_xl2[s*OUTC + c1];
        float t0 = l0 + xr0; t0 = t0>0.f? t0 : 0.2f*t0;
        float t1 = l1 + xr1v; t1 = t1>0.f? t1 : 0.2f*t1;
        float p = t0*a0 + t1*a1;
        #pragma unroll
        for (int o=16;o;o>>=1) p += __shfl_xor_sync(0xffffffffu, p, o);
        float mn = fmaxf(m, p);
        float sc = __expf(m - mn);
        float wv = __expf(p - mn);
        den = den*sc + wv;
        s0 = s0*sc + wv*l0;
        s1 = s1*sc + wv*l1;
        m = mn;
    }
    float inv = 1.f/den;
    out[d*OUTC + c0] = s0*inv + bias[c0];
    out[d*OUTC + c1] = s1*inv + bias[c1];
}

// ---------------- host launch ----------------
extern "C" void kernel_launch(void* const* d_in, const int* in_sizes, int n_in,
                              void* d_out, int out_size){
    const int*   eib   = (const int*)d_in[0];
    const float* ve    = (const float*)d_in[1];
    const float* ac    = (const float*)d_in[2];
    const float* man   = (const float*)d_in[3];
    const float* mask  = (const float*)d_in[4];
    // d_in[5] graph_matrix unused (overwritten in reference)
    const float* c1w   = (const float*)d_in[6];
    const float* c1b   = (const float*)d_in[7];
    const float* bn1g  = (const float*)d_in[8];
    const float* bn1b  = (const float*)d_in[9];
    const float* c2w   = (const float*)d_in[10];
    const float* c2b   = (const float*)d_in[11];
    const float* bn2g  = (const float*)d_in[12];
    const float* bn2b  = (const float*)d_in[13];
    const float* gwih  = (const float*)d_in[14];
    const float* gwhh  = (const float*)d_in[15];
    const float* gbih  = (const float*)d_in[16];
    const float* gbhh  = (const float*)d_in[17];
    const float* g1wl  = (const float*)d_in[18];
    const float* g1bl  = (const float*)d_in[19];
    const float* g1wr  = (const float*)d_in[20];
    const float* g1br  = (const float*)d_in[21];
    const float* g1att = (const float*)d_in[22];
    const float* g1bias= (const float*)d_in[23];
    const float* g2wl  = (const float*)d_in[24];
    const float* g2bl  = (const float*)d_in[25];
    const float* g2wr  = (const float*)d_in[26];
    const float* g2br  = (const float*)d_in[27];
    const float* g2att = (const float*)d_in[28];
    const float* g2bias= (const float*)d_in[29];
    float* out = (float*)d_out;

    k_init<<<(NTOT+255)/256, 256>>>();
    k_conv1<<<(BB*POS+255)/256, 256>>>(man, ac, ve, c1w, c1b, bn1g, bn1b);
    k_conv2<<<dim3(BB, (POS+255)/256), 256>>>(c2w, c2b, bn2g, bn2b, gwih, gbih);
    k_gru<<<(NTOT+255)/256, 256>>>(man, mask, gwhh, gbhh);
    k_hist<<<(ET+255)/256, 256>>>(eib);
    k_scan<<<1, 1024>>>();
    k_scatter<<<(ET+255)/256, 256>>>(eib);
    // GAT layer 1 projections: (4992x78) @ (512x78)^T
    k_gemm<<<dim3(D1/64, NTOT/64), 256>>>(0, g1wl, g1bl, D1, F1);
    k_gemm<<<dim3(D1/64, NTOT/64), 256>>>(1, g1wr, g1br, D1, F1);
    k_gat1<<<NTOT, 256>>>(g1att, g1bias);
    // GAT layer 2 projections: (4992x512) @ (64x512)^T
    k_gemm<<<dim3(OUTC/64, NTOT/64), 256>>>(2, g2wl, g2bl, OUTC, D1);
    k_gemm<<<dim3(OUTC/64, NTOT/64), 256>>>(3, g2wr, g2br, OUTC, D1);
    k_gat2<<<(NTOT+7)/8, 256>>>(g2att, g2bias, out);
}

// round 2
// speedup vs baseline: 1.2416x; 1.2416x over previous
#include <cuda_runtime.h>
#include <math.h>

#define NTOT 4992
#define BB 128
#define HN 39
#define WN 39
#define POS 1521      // 39*39
#define E0 200064     // B*E_PER
#define ET 205056     // E0 + NTOT self loops
#define HEADS 8
#define HID 64
#define OUTC 64
#define F1 78
#define D1 512

// ---------------- scratch (static device memory; no allocation) ----------------
__device__ float d_x1[BB*8*POS];      // conv1 output (B,8,39,39)
__device__ float d_gi[3*HN*NTOT];     // GRU input gates, plane layout [(t*3+g)][node]
__device__ float d_xnT[F1*NTOT];      // node features TRANSPOSED (78, N)
__device__ float d_xl1[NTOT*D1];
__device__ float d_xr1[NTOT*D1];
__device__ float d_h1[NTOT*D1];
__device__ float d_xl2[NTOT*OUTC];
__device__ float d_xr2[NTOT*OUTC];
__device__ int   d_deg[NTOT];
__device__ int   d_off[NTOT+1];
__device__ int   d_cur[NTOT];
__device__ int   d_csr[ET];

__device__ __forceinline__ float nz(float v){ return isnan(v) ? 0.0f : v; }
__device__ __forceinline__ float fast_tanh(float x){
    float r; asm("tanh.approx.f32 %0, %1;" : "=f"(r) : "f"(x)); return r;
}
__device__ __forceinline__ float fast_sig(float x){
    return __fdividef(1.0f, 1.0f + __expf(-x));
}

// ---------------- init ----------------
__global__ void k_init(){
    int i = blockIdx.x*blockDim.x + threadIdx.x;
    if (i < NTOT) d_deg[i] = 0;
}

// ---------------- conv1 (1x1, 3->8) + BN + ReLU ----------------
__global__ void k_conv1(const float* __restrict__ man, const float* __restrict__ ac,
                        const float* __restrict__ ve,
                        const float* __restrict__ w1, const float* __restrict__ b1,
                        const float* __restrict__ g1, const float* __restrict__ bb1){
    int idx = blockIdx.x*blockDim.x + threadIdx.x;
    if (idx >= BB*POS) return;
    int b = idx / POS, p = idx % POS;
    float c0 = nz(man[idx]), c1 = nz(ac[idx]), c2 = nz(ve[idx]);
    const float inv = rsqrtf(1.0f + 1e-5f);
    #pragma unroll
    for (int o=0;o<8;o++){
        float v = w1[o*3+0]*c0 + w1[o*3+1]*c1 + w1[o*3+2]*c2 + b1[o];
        v = v * (g1[o]*inv) + bb1[o];
        d_x1[(b*8+o)*POS + p] = fmaxf(v, 0.0f);
    }
}

// ---------------- conv2 (3x3 pad1, 8->16) + BN + GRU input projection (16->3) ----------------
__global__ void k_conv2(const float* __restrict__ w2, const float* __restrict__ b2,
                        const float* __restrict__ g2, const float* __restrict__ bb2,
                        const float* __restrict__ wih, const float* __restrict__ bih){
    __shared__ float sw2[1152];
    __shared__ float ssc[16], sof[16];
    __shared__ float swih[48];
    int tid = threadIdx.x;
    for (int i=tid;i<1152;i+=blockDim.x) sw2[i]=w2[i];
    if (tid<16){ float s = g2[tid]*rsqrtf(1.0f+1e-5f); ssc[tid]=s; sof[tid]=b2[tid]*s + bb2[tid]; }
    if (tid<48) swih[tid]=wih[tid];
    __syncthreads();
    int b = blockIdx.x;
    int p = blockIdx.y*blockDim.x + tid;
    if (p >= POS) return;
    int i = p / WN, j = p % WN;
    float acc[16];
    #pragma unroll
    for (int o=0;o<16;o++) acc[o]=0.f;
    const float* x1b = d_x1 + b*8*POS;
    for (int c=0;c<8;c++){
        #pragma unroll
        for (int di=0;di<3;di++){
            int ii = i+di-1; if (ii<0||ii>=HN) continue;
            #pragma unroll
            for (int dj=0;dj<3;dj++){
                int jj = j+dj-1; if (jj<0||jj>=WN) continue;
                float v = x1b[c*POS + ii*WN + jj];
                #pragma unroll
                for (int o=0;o<16;o++) acc[o] += sw2[o*72 + c*9 + di*3 + dj]*v;
            }
        }
    }
    float q0=bih[0], q1=bih[1], q2=bih[2];
    #pragma unroll
    for (int o=0;o<16;o++){
        float x2 = acc[o]*ssc[o] + sof[o];
        q0 += swih[0*16+o]*x2;
        q1 += swih[1*16+o]*x2;
        q2 += swih[2*16+o]*x2;
    }
    // plane layout: gate g at time t: d_gi[(t*3+g)*NTOT + node], node = b*WN + j
    int node = b*WN + j;
    int base = (i*3)*NTOT + node;
    d_gi[base          ] = q0;
    d_gi[base +   NTOT ] = q1;
    d_gi[base + 2*NTOT ] = q2;
}

// ---------------- GRU over rows + masked feature assembly -> xnT (78, N) ----------------
__global__ void k_gru(const float* __restrict__ man, const float* __restrict__ maskv,
                      const float* __restrict__ whh, const float* __restrict__ bhh){
    int node = blockIdx.x*blockDim.x + threadIdx.x;
    if (node >= NTOT) return;
    int b = node / WN, w = node % WN;
    float mk = maskv[node];
    // man part (features 0..38), transposed coalesced writes
    #pragma unroll 4
    for (int f=0; f<HN; f++)
        d_xnT[f*NTOT + node] = nz(man[(b*HN+f)*WN + w]) * mk;

    float w0=whh[0], w1=whh[1], w2=whh[2];
    float bh0=bhh[0], bh1=bhh[1], bh2=bhh[2];
    float h = 0.f;
    // prefetch t=0
    float p0 = d_gi[node], p1 = d_gi[NTOT + node], p2 = d_gi[2*NTOT + node];
    for (int t=0;t<HN;t++){
        float c0=p0, c1=p1, c2=p2;
        if (t+1 < HN){
            int base = ((t+1)*3)*NTOT + node;
            p0 = d_gi[base]; p1 = d_gi[base+NTOT]; p2 = d_gi[base+2*NTOT];
        }
        float r = fast_sig(c0 + w0*h + bh0);
        float z = fast_sig(c1 + w1*h + bh1);
        float n = fast_tanh(c2 + r*(w2*h + bh2));
        h = (1.f-z)*n + z*h;
        d_xnT[(HN+t)*NTOT + node] = h*mk;
    }
}

// ---------------- CSR build (group edges by dst) ----------------
__global__ void k_hist(const int* __restrict__ eib){
    int e = blockIdx.x*blockDim.x + threadIdx.x;
    if (e >= ET) return;
    int dst = (e < E0) ? eib[E0 + e] : (e - E0);
    atomicAdd(&d_deg[dst], 1);
}

__global__ void k_scan(){      // single block, 1024 threads, chunk=5
    __shared__ int s[1024];
    int t = threadIdx.x;
    int loc[5]; int sum=0;
    #pragma unroll
    for (int k=0;k<5;k++){
        int i=t*5+k;
        int v = (i<NTOT)? d_deg[i]:0;
        loc[k]=sum; sum+=v;
    }
    s[t]=sum; __syncthreads();
    for (int dd=1; dd<1024; dd<<=1){
        int v = (t>=dd) ? s[t-dd] : 0;
        __syncthreads();
        s[t]+=v;
        __syncthreads();
    }
    int base = (t==0)?0 : s[t-1];
    #pragma unroll
    for (int k=0;k<5;k++){
        int i=t*5+k;
        if (i<NTOT){ int v = base+loc[k]; d_off[i]=v; d_cur[i]=v; }
    }
    if (t==1023) d_off[NTOT] = s[1023];
}

__global__ void k_scatter(const int* __restrict__ eib){
    int e = blockIdx.x*blockDim.x + threadIdx.x;
    if (e >= ET) return;
    int src, dst;
    if (e < E0){ src = eib[e]; dst = eib[E0+e]; }
    else { src = dst = e - E0; }
    int pos = atomicAdd(&d_cur[dst], 1);
    d_csr[pos] = src;
}

// ---------------- fused projection GEMM: computes BOTH xl and xr halves ----------------
// layer 1: A = d_xnT (transposed, [78][N]), K=78, Mh=512, C -> d_xl1/d_xr1
// layer 2: A = d_h1  (row-major, [N][512]), K=512, Mh=64,  C -> d_xl2/d_xr2
__global__ void k_proj(int layer,
                       const float* __restrict__ Wl, const float* __restrict__ bl,
                       const float* __restrict__ Wr, const float* __restrict__ br){
    const int K  = (layer==1) ? F1 : D1;
    const int Mh = (layer==1) ? D1 : OUTC;
    int m0g = blockIdx.x*64;
    bool isR = (m0g >= Mh);
    const float* W    = isR ? Wr : Wl;
    const float* bias = isR ? br : bl;
    int m0 = isR ? (m0g - Mh) : m0g;
    float* C;
    if (layer==1) C = isR ? d_xr1 : d_xl1;
    else          C = isR ? d_xr2 : d_xl2;
    int n0 = blockIdx.y*64;

    __shared__ float As[16][68];   // [k][node]
    __shared__ float Ws[16][68];   // [k][m]
    int tid = threadIdx.x;
    int tx = tid & 15, ty = tid >> 4;
    float acc[4][4] = {};

    for (int k0=0; k0<K; k0+=16){
        // load A tile -> As[k][n]
        if (layer==1){
            #pragma unroll
            for (int q=0;q<4;q++){
                int idx = tid + q*256;
                int k = idx >> 6, n = idx & 63;
                As[k][n] = (k0+k < K) ? d_xnT[(k0+k)*NTOT + n0+n] : 0.f;
            }
        } else {
            #pragma unroll
            for (int q=0;q<4;q++){
                int idx = tid + q*256;
                int r = idx >> 4, c = idx & 15;
                As[c][r] = d_h1[(n0+r)*D1 + k0+c];   // K=512, always in range
            }
        }
        // load W tile transposed -> Ws[k][m]
        #pragma unroll
        for (int q=0;q<4;q++){
            int idx = tid + q*256;
            int r = idx >> 4, c = idx & 15;
            Ws[c][r] = (k0+c < K) ? W[(m0+r)*K + k0+c] : 0.f;
        }
        __syncthreads();
        #pragma unroll
        for (int kk=0;kk<16;kk++){
            float4 a = *reinterpret_cast<const float4*>(&As[kk][ty*4]);
            float4 wv = *reinterpret_cast<const float4*>(&Ws[kk][tx*4]);
            float av[4] = {a.x,a.y,a.z,a.w};
            float wvv[4] = {wv.x,wv.y,wv.z,wv.w};
            #pragma unroll
            for (int i=0;i<4;i++)
                #pragma unroll
                for (int j=0;j<4;j++) acc[i][j] += av[i]*wvv[j];
        }
        __syncthreads();
    }
    #pragma unroll
    for (int i=0;i<4;i++){
        int n = n0 + ty*4 + i;
        #pragma unroll
        for (int j=0;j<4;j++){
            int m = m0 + tx*4 + j;
            C[n*Mh + m] = acc[i][j] + bias[m];
        }
    }
}

// ---------------- online-softmax update (warp-uniform p) ----------------
#define OSM_UPDATE(p, l0, l1)                                   \
    do {                                                        \
        if ((p) <= m){                                          \
            float wv_ = __expf((p) - m);                        \
            den += wv_; s0 += wv_*(l0); s1 += wv_*(l1);         \
        } else {                                                \
            float sc_ = __expf(m - (p));                        \
            den = den*sc_ + 1.f;                                \
            s0  = s0*sc_ + (l0);                                \
            s1  = s1*sc_ + (l1);                                \
            m = (p);                                            \
        }                                                       \
    } while(0)

__device__ __forceinline__ float warp_sum(float p){
    #pragma unroll
    for (int o=16;o;o>>=1) p += __shfl_xor_sync(0xffffffffu, p, o);
    return p;
}

// ---------------- GAT1 aggregation: one-pass online softmax, warp per (dst,head) ----------------
__global__ void k_gat1(const float* __restrict__ att, const float* __restrict__ bias){
    int d = blockIdx.x;
    int h = threadIdx.x >> 5, lane = threadIdx.x & 31;
    int c0 = h*HID + lane, c1 = c0 + 32;
    float xr0 = d_xr1[d*D1 + c0], xr1v = d_xr1[d*D1 + c1];
    float a0 = att[c0], a1 = att[c1];
    float m = -INFINITY, den = 0.f, s0 = 0.f, s1 = 0.f;
    int eb = d_off[d], ee = d_off[d+1];
    int e = eb;
    for (; e+1<ee; e+=2){
        int sA = d_csr[e], sB = d_csr[e+1];
        float lA0 = d_xl1[sA*D1 + c0], lA1 = d_xl1[sA*D1 + c1];
        float lB0 = d_xl1[sB*D1 + c0], lB1 = d_xl1[sB*D1 + c1];
        float tA0 = lA0 + xr0;  tA0 = tA0>0.f? tA0 : 0.2f*tA0;
        float tA1 = lA1 + xr1v; tA1 = tA1>0.f? tA1 : 0.2f*tA1;
        float tB0 = lB0 + xr0;  tB0 = tB0>0.f? tB0 : 0.2f*tB0;
        float tB1 = lB1 + xr1v; tB1 = tB1>0.f? tB1 : 0.2f*tB1;
        float pA = warp_sum(tA0*a0 + tA1*a1);
        float pB = warp_sum(tB0*a0 + tB1*a1);
        OSM_UPDATE(pA, lA0, lA1);
        OSM_UPDATE(pB, lB0, lB1);
    }
    if (e < ee){
        int s = d_csr[e];
        float l0 = d_xl1[s*D1 + c0], l1 = d_xl1[s*D1 + c1];
        float t0 = l0 + xr0;  t0 = t0>0.f? t0 : 0.2f*t0;
        float t1 = l1 + xr1v; t1 = t1>0.f? t1 : 0.2f*t1;
        float p = warp_sum(t0*a0 + t1*a1);
        OSM_UPDATE(p, l0, l1);
    }
    float inv = __fdividef(1.f, den);
    float o0 = s0*inv + bias[c0];
    float o1 = s1*inv + bias[c1];
    d_h1[d*D1 + c0] = o0>0.f? o0 : (__expf(o0)-1.f);   // ELU
    d_h1[d*D1 + c1] = o1>0.f? o1 : (__expf(o1)-1.f);
}

// ---------------- GAT2 aggregation: warp per dst (1 head, 64 ch) ----------------
__global__ void k_gat2(const float* __restrict__ att, const float* __restrict__ bias,
                       float* __restrict__ out){
    int d = blockIdx.x*8 + (threadIdx.x>>5);
    int lane = threadIdx.x & 31;
    if (d >= NTOT) return;
    int c0 = lane, c1 = lane+32;
    float xr0 = d_xr2[d*OUTC + c0], xr1v = d_xr2[d*OUTC + c1];
    float a0 = att[c0], a1 = att[c1];
    float m = -INFINITY, den = 0.f, s0 = 0.f, s1 = 0.f;
    int eb = d_off[d], ee = d_off[d+1];
    int e = eb;
    for (; e+1<ee; e+=2){
        int sA = d_csr[e], sB = d_csr[e+1];
        float lA0 = d_xl2[sA*OUTC + c0], lA1 = d_xl2[sA*OUTC + c1];
        float lB0 = d_xl2[sB*OUTC + c0], lB1 = d_xl2[sB*OUTC + c1];
        float tA0 = lA0 + xr0;  tA0 = tA0>0.f? tA0 : 0.2f*tA0;
        float tA1 = lA1 + xr1v; tA1 = tA1>0.f? tA1 : 0.2f*tA1;
        float tB0 = lB0 + xr0;  tB0 = tB0>0.f? tB0 : 0.2f*tB0;
        float tB1 = lB1 + xr1v; tB1 = tB1>0.f? tB1 : 0.2f*tB1;
        float pA = warp_sum(tA0*a0 + tA1*a1);
        float pB = warp_sum(tB0*a0 + tB1*a1);
        OSM_UPDATE(pA, lA0, lA1);
        OSM_UPDATE(pB, lB0, lB1);
    }
    if (e < ee){
        int s = d_csr[e];
        float l0 = d_xl2[s*OUTC + c0], l1 = d_xl2[s*OUTC + c1];
        float t0 = l0 + xr0;  t0 = t0>0.f? t0 : 0.2f*t0;
        float t1 = l1 + xr1v; t1 = t1>0.f? t1 : 0.2f*t1;
        float p = warp_sum(t0*a0 + t1*a1);
        OSM_UPDATE(p, l0, l1);
    }
    float inv = __fdividef(1.f, den);
    out[d*OUTC + c0] = s0*inv + bias[c0];
    out[d*OUTC + c1] = s1*inv + bias[c1];
}

// ---------------- host launch ----------------
extern "C" void kernel_launch(void* const* d_in, const int* in_sizes, int n_in,
                              void* d_out, int out_size){
    const int*   eib   = (const int*)d_in[0];
    const float* ve    = (const float*)d_in[1];
    const float* ac    = (const float*)d_in[2];
    const float* man   = (const float*)d_in[3];
    const float* mask  = (const float*)d_in[4];
    const float* c1w   = (const float*)d_in[6];
    const float* c1b   = (const float*)d_in[7];
    const float* bn1g  = (const float*)d_in[8];
    const float* bn1b  = (const float*)d_in[9];
    const float* c2w   = (const float*)d_in[10];
    const float* c2b   = (const float*)d_in[11];
    const float* bn2g  = (const float*)d_in[12];
    const float* bn2b  = (const float*)d_in[13];
    const float* gwih  = (const float*)d_in[14];
    const float* gwhh  = (const float*)d_in[15];
    const float* gbih  = (const float*)d_in[16];
    const float* gbhh  = (const float*)d_in[17];
    const float* g1wl  = (const float*)d_in[18];
    const float* g1bl  = (const float*)d_in[19];
    const float* g1wr  = (const float*)d_in[20];
    const float* g1br  = (const float*)d_in[21];
    const float* g1att = (const float*)d_in[22];
    const float* g1bias= (const float*)d_in[23];
    const float* g2wl  = (const float*)d_in[24];
    const float* g2bl  = (const float*)d_in[25];
    const float* g2wr  = (const float*)d_in[26];
    const float* g2br  = (const float*)d_in[27];
    const float* g2att = (const float*)d_in[28];
    const float* g2bias= (const float*)d_in[29];
    float* out = (float*)d_out;

    k_init<<<(NTOT+255)/256, 256>>>();
    k_conv1<<<(BB*POS+255)/256, 256>>>(man, ac, ve, c1w, c1b, bn1g, bn1b);
    k_conv2<<<dim3(BB, (POS+255)/256), 256>>>(c2w, c2b, bn2g, bn2b, gwih, gbih);
    k_gru<<<(NTOT+255)/256, 256>>>(man, mask, gwhh, gbhh);
    k_hist<<<(ET+255)/256, 256>>>(eib);
    k_scan<<<1, 1024>>>();
    k_scatter<<<(ET+255)/256, 256>>>(eib);
    // layer 1 projections: both halves (M = 2*512 = 1024)
    k_proj<<<dim3(2*D1/64, NTOT/64), 256>>>(1, g1wl, g1bl, g1wr, g1br);
    k_gat1<<<NTOT, 256>>>(g1att, g1bias);
    // layer 2 projections: both halves (M = 2*64 = 128)
    k_proj<<<dim3(2*OUTC/64, NTOT/64), 256>>>(2, g2wl, g2bl, g2wr, g2br);
    k_gat2<<<(NTOT+7)/8, 256>>>(g2att, g2bias, out);
}

// round 3
// speedup vs baseline: 1.4025x; 1.1296x over previous
#include <cuda_runtime.h>
#include <math.h>

#define NTOT 4992
#define BB 128
#define HN 39
#define WN 39
#define POS 1521      // 39*39
#define E0 200064     // B*E_PER
#define ET 205056     // E0 + NTOT self loops
#define HEADS 8
#define HID 64
#define OUTC 64
#define F1 78
#define D1 512

// ---------------- scratch (static device memory; no allocation) ----------------
__device__ float d_x1[BB*8*POS];      // conv1 output (B,8,39,39)
__device__ float d_gi[3*HN*NTOT];     // GRU input gates, plane layout [(t*3+g)][node]
__device__ float d_xnT[F1*NTOT];      // node features TRANSPOSED (78, N)
__device__ float d_xl1[NTOT*D1];
__device__ float d_xr1[NTOT*D1];
__device__ float d_h1[NTOT*D1];
__device__ float d_xl2[NTOT*OUTC];
__device__ float d_xr2[NTOT*OUTC];
__device__ int   d_deg[NTOT];
__device__ int   d_off[NTOT+1];
__device__ int   d_cur[NTOT];
__device__ int   d_csr[ET];

__device__ __forceinline__ float nz(float v){ return isnan(v) ? 0.0f : v; }
__device__ __forceinline__ float fast_tanh(float x){
    float r; asm("tanh.approx.f32 %0, %1;" : "=f"(r) : "f"(x)); return r;
}
__device__ __forceinline__ float fast_sig(float x){
    return __fdividef(1.0f, 1.0f + __expf(-x));
}

// ------ f32x2 packed math helpers ------
__device__ __forceinline__ unsigned long long pack2(float lo, float hi){
    unsigned long long r;
    asm("mov.b64 %0, {%1,%2};" : "=l"(r) : "f"(lo), "f"(hi));
    return r;
}
__device__ __forceinline__ unsigned long long fma2(unsigned long long a,
                                                   unsigned long long b,
                                                   unsigned long long c){
    unsigned long long d;
    asm("fma.rn.f32x2 %0, %1, %2, %3;" : "=l"(d) : "l"(a), "l"(b), "l"(c));
    return d;
}
__device__ __forceinline__ void unpack2(unsigned long long v, float& lo, float& hi){
    asm("mov.b64 {%0,%1}, %2;" : "=f"(lo), "=f"(hi) : "l"(v));
}

// ---------------- init ----------------
__global__ void k_init(){
    int i = blockIdx.x*blockDim.x + threadIdx.x;
    if (i < NTOT) d_deg[i] = 0;
}

// ---------------- conv1 (1x1, 3->8) + BN + ReLU ----------------
__global__ void k_conv1(const float* __restrict__ man, const float* __restrict__ ac,
                        const float* __restrict__ ve,
                        const float* __restrict__ w1, const float* __restrict__ b1,
                        const float* __restrict__ g1, const float* __restrict__ bb1){
    int idx = blockIdx.x*blockDim.x + threadIdx.x;
    if (idx >= BB*POS) return;
    int b = idx / POS, p = idx % POS;
    float c0 = nz(man[idx]), c1 = nz(ac[idx]), c2 = nz(ve[idx]);
    const float inv = rsqrtf(1.0f + 1e-5f);
    #pragma unroll
    for (int o=0;o<8;o++){
        float v = w1[o*3+0]*c0 + w1[o*3+1]*c1 + w1[o*3+2]*c2 + b1[o];
        v = v * (g1[o]*inv) + bb1[o];
        d_x1[(b*8+o)*POS + p] = fmaxf(v, 0.0f);
    }
}

// ---------------- conv2 (3x3 pad1, 8->16) + BN + GRU input projection (16->3) ----------------
__global__ void k_conv2(const float* __restrict__ w2, const float* __restrict__ b2,
                        const float* __restrict__ g2, const float* __restrict__ bb2,
                        const float* __restrict__ wih, const float* __restrict__ bih){
    __shared__ float sw2[1152];
    __shared__ float ssc[16], sof[16];
    __shared__ float swih[48];
    int tid = threadIdx.x;
    for (int i=tid;i<1152;i+=blockDim.x) sw2[i]=w2[i];
    if (tid<16){ float s = g2[tid]*rsqrtf(1.0f+1e-5f); ssc[tid]=s; sof[tid]=b2[tid]*s + bb2[tid]; }
    if (tid<48) swih[tid]=wih[tid];
    __syncthreads();
    int b = blockIdx.x;
    int p = blockIdx.y*blockDim.x + tid;
    if (p >= POS) return;
    int i = p / WN, j = p % WN;
    float acc[16];
    #pragma unroll
    for (int o=0;o<16;o++) acc[o]=0.f;
    const float* x1b = d_x1 + b*8*POS;
    for (int c=0;c<8;c++){
        #pragma unroll
        for (int di=0;di<3;di++){
            int ii = i+di-1; if (ii<0||ii>=HN) continue;
            #pragma unroll
            for (int dj=0;dj<3;dj++){
                int jj = j+dj-1; if (jj<0||jj>=WN) continue;
                float v = x1b[c*POS + ii*WN + jj];
                #pragma unroll
                for (int o=0;o<16;o++) acc[o] += sw2[o*72 + c*9 + di*3 + dj]*v;
            }
        }
    }
    float q0=bih[0], q1=bih[1], q2=bih[2];
    #pragma unroll
    for (int o=0;o<16;o++){
        float x2 = acc[o]*ssc[o] + sof[o];
        q0 += swih[0*16+o]*x2;
        q1 += swih[1*16+o]*x2;
        q2 += swih[2*16+o]*x2;
    }
    int node = b*WN + j;
    int base = (i*3)*NTOT + node;
    d_gi[base          ] = q0;
    d_gi[base +   NTOT ] = q1;
    d_gi[base + 2*NTOT ] = q2;
}

// ---------------- man-part feature copy (independent of recurrence) ----------------
__global__ void k_man(const float* __restrict__ man, const float* __restrict__ maskv){
    int idx = blockIdx.x*blockDim.x + threadIdx.x;
    if (idx >= HN*NTOT) return;
    int f = idx / NTOT, node = idx % NTOT;
    int b = node / WN, w = node % WN;
    float mk = maskv[node];
    d_xnT[f*NTOT + node] = nz(man[(b*HN+f)*WN + w]) * mk;
}

// ---------------- GRU over rows -> xnT rows 39..77 ----------------
__global__ void k_gru(const float* __restrict__ maskv,
                      const float* __restrict__ whh, const float* __restrict__ bhh){
    int node = blockIdx.x*64 + threadIdx.x;
    if (node >= NTOT) return;
    float mk = maskv[node];
    float w0=whh[0], w1=whh[1], w2=whh[2];
    float bh0=bhh[0], bh1=bhh[1], bh2=bhh[2];
    float h = 0.f;
    // depth-2 prefetch
    float a0 = d_gi[node],        a1 = d_gi[NTOT + node],   a2 = d_gi[2*NTOT + node];
    float b0 = d_gi[3*NTOT+node], b1 = d_gi[4*NTOT + node], b2 = d_gi[5*NTOT + node];
    #pragma unroll 1
    for (int t=0;t<HN;t++){
        float c0=a0, c1=a1, c2=a2;
        a0=b0; a1=b1; a2=b2;
        if (t+2 < HN){
            int base = ((t+2)*3)*NTOT + node;
            b0 = d_gi[base]; b1 = d_gi[base+NTOT]; b2 = d_gi[base+2*NTOT];
        }
        float r = fast_sig(c0 + w0*h + bh0);
        float z = fast_sig(c1 + w1*h + bh1);
        float n = fast_tanh(c2 + r*(w2*h + bh2));
        h = (1.f-z)*n + z*h;
        d_xnT[(HN+t)*NTOT + node] = h*mk;
    }
}

// ---------------- CSR build (group edges by dst) ----------------
__global__ void k_hist(const int* __restrict__ eib){
    int e = blockIdx.x*blockDim.x + threadIdx.x;
    if (e >= ET) return;
    int dst = (e < E0) ? eib[E0 + e] : (e - E0);
    atomicAdd(&d_deg[dst], 1);
}

__global__ void k_scan(){      // single block, 1024 threads, chunk=5
    __shared__ int s[1024];
    int t = threadIdx.x;
    int loc[5]; int sum=0;
    #pragma unroll
    for (int k=0;k<5;k++){
        int i=t*5+k;
        int v = (i<NTOT)? d_deg[i]:0;
        loc[k]=sum; sum+=v;
    }
    s[t]=sum; __syncthreads();
    for (int dd=1; dd<1024; dd<<=1){
        int v = (t>=dd) ? s[t-dd] : 0;
        __syncthreads();
        s[t]+=v;
        __syncthreads();
    }
    int base = (t==0)?0 : s[t-1];
    #pragma unroll
    for (int k=0;k<5;k++){
        int i=t*5+k;
        if (i<NTOT){ int v = base+loc[k]; d_off[i]=v; d_cur[i]=v; }
    }
    if (t==1023) d_off[NTOT] = s[1023];
}

__global__ void k_scatter(const int* __restrict__ eib){
    int e = blockIdx.x*blockDim.x + threadIdx.x;
    if (e >= ET) return;
    int src, dst;
    if (e < E0){ src = eib[e]; dst = eib[E0+e]; }
    else { src = dst = e - E0; }
    int pos = atomicAdd(&d_cur[dst], 1);
    d_csr[pos] = src;
}

// ---------------- fused projection GEMM (f32x2 packed FMA) ----------------
// layer 1: A = d_xnT ([78][N]), K=78, Mh=512, C -> d_xl1/d_xr1
// layer 2: A = d_h1  ([N][512]), K=512, Mh=64,  C -> d_xl2/d_xr2
__global__ void k_proj(int layer,
                       const float* __restrict__ Wl, const float* __restrict__ bl,
                       const float* __restrict__ Wr, const float* __restrict__ br){
    const int K  = (layer==1) ? F1 : D1;
    const int Mh = (layer==1) ? D1 : OUTC;
    int m0g = blockIdx.x*64;
    bool isR = (m0g >= Mh);
    const float* W    = isR ? Wr : Wl;
    const float* bias = isR ? br : bl;
    int m0 = isR ? (m0g - Mh) : m0g;
    float* C;
    if (layer==1) C = isR ? d_xr1 : d_xl1;
    else          C = isR ? d_xr2 : d_xl2;
    int n0 = blockIdx.y*64;

    __shared__ float As[16][68];   // [k][node]
    __shared__ float Ws[16][68];   // [k][m]
    int tid = threadIdx.x;
    int tx = tid & 15, ty = tid >> 4;
    unsigned long long acc01[4] = {0ull,0ull,0ull,0ull};
    unsigned long long acc23[4] = {0ull,0ull,0ull,0ull};

    for (int k0=0; k0<K; k0+=16){
        if (layer==1){
            #pragma unroll
            for (int q=0;q<4;q++){
                int idx = tid + q*256;
                int k = idx >> 6, n = idx & 63;
                As[k][n] = (k0+k < K) ? d_xnT[(k0+k)*NTOT + n0+n] : 0.f;
            }
        } else {
            #pragma unroll
            for (int q=0;q<4;q++){
                int idx = tid + q*256;
                int r = idx >> 4, c = idx & 15;
                As[c][r] = d_h1[(n0+r)*D1 + k0+c];
            }
        }
        #pragma unroll
        for (int q=0;q<4;q++){
            int idx = tid + q*256;
            int r = idx >> 4, c = idx & 15;
            Ws[c][r] = (k0+c < K) ? W[(m0+r)*K + k0+c] : 0.f;
        }
        __syncthreads();
        #pragma unroll
        for (int kk=0;kk<16;kk++){
            float4 a4 = *reinterpret_cast<const float4*>(&As[kk][ty*4]);
            float4 w4 = *reinterpret_cast<const float4*>(&Ws[kk][tx*4]);
            unsigned long long w01 = pack2(w4.x, w4.y);
            unsigned long long w23 = pack2(w4.z, w4.w);
            float av[4] = {a4.x, a4.y, a4.z, a4.w};
            #pragma unroll
            for (int i=0;i<4;i++){
                unsigned long long aa = pack2(av[i], av[i]);
                acc01[i] = fma2(aa, w01, acc01[i]);
                acc23[i] = fma2(aa, w23, acc23[i]);
            }
        }
        __syncthreads();
    }
    #pragma unroll
    for (int i=0;i<4;i++){
        int n = n0 + ty*4 + i;
        float v0,v1,v2,v3;
        unpack2(acc01[i], v0, v1);
        unpack2(acc23[i], v2, v3);
        int m = m0 + tx*4;
        C[n*Mh + m+0] = v0 + bias[m+0];
        C[n*Mh + m+1] = v1 + bias[m+1];
        C[n*Mh + m+2] = v2 + bias[m+2];
        C[n*Mh + m+3] = v3 + bias[m+3];
    }
}

// ---------------- GAT1 aggregation: 4 edges/iter, 8-lane groups, softmax (no max shift) ----------------
__global__ void k_gat1(const float* __restrict__ att, const float* __restrict__ bias){
    int d = blockIdx.x;
    int h = threadIdx.x >> 5, lane = threadIdx.x & 31;
    int g = lane >> 3, l8 = lane & 7;
    int col = h*HID + l8*8;
    const float4* xr4 = reinterpret_cast<const float4*>(&d_xr1[d*D1 + col]);
    float4 xrA = xr4[0], xrB = xr4[1];
    const float4* at4 = reinterpret_cast<const float4*>(&att[col]);
    float4 atA = at4[0], atB = at4[1];

    float den = 0.f;
    float s[8] = {0,0,0,0,0,0,0,0};
    int eb = d_off[d], ee = d_off[d+1];
    #pragma unroll 2
    for (int e0 = eb; e0 < ee; e0 += 4){
        int e = e0 + g;
        bool valid = (e < ee);
        int src = d_csr[valid ? e : eb];
        const float4* xl4 = reinterpret_cast<const float4*>(&d_xl1[src*D1 + col]);
        float4 lA = xl4[0], lB = xl4[1];
        float t, q;
        t = lA.x + xrA.x; t = t>0.f? t : 0.2f*t; q  = atA.x*t;
        t = lA.y + xrA.y; t = t>0.f? t : 0.2f*t; q += atA.y*t;
        t = lA.z + xrA.z; t = t>0.f? t : 0.2f*t; q += atA.z*t;
        t = lA.w + xrA.w; t = t>0.f? t : 0.2f*t; q += atA.w*t;
        t = lB.x + xrB.x; t = t>0.f? t : 0.2f*t; q += atB.x*t;
        t = lB.y + xrB.y; t = t>0.f? t : 0.2f*t; q += atB.y*t;
        t = lB.z + xrB.z; t = t>0.f? t : 0.2f*t; q += atB.z*t;
        t = lB.w + xrB.w; t = t>0.f? t : 0.2f*t; q += atB.w*t;
        q += __shfl_xor_sync(0xffffffffu, q, 1);
        q += __shfl_xor_sync(0xffffffffu, q, 2);
        q += __shfl_xor_sync(0xffffffffu, q, 4);
        float wv = valid ? __expf(q) : 0.f;
        den += wv;
        s[0] += wv*lA.x; s[1] += wv*lA.y; s[2] += wv*lA.z; s[3] += wv*lA.w;
        s[4] += wv*lB.x; s[5] += wv*lB.y; s[6] += wv*lB.z; s[7] += wv*lB.w;
    }
    #pragma unroll
    for (int o=8;o<=16;o<<=1){
        den += __shfl_xor_sync(0xffffffffu, den, o);
        #pragma unroll
        for (int k=0;k<8;k++) s[k] += __shfl_xor_sync(0xffffffffu, s[k], o);
    }
    if (g == 0){
        float inv = __fdividef(1.f, den);
        float o0;
        float4 rA, rB;
        o0 = s[0]*inv + bias[col+0]; rA.x = o0>0.f? o0 : (__expf(o0)-1.f);
        o0 = s[1]*inv + bias[col+1]; rA.y = o0>0.f? o0 : (__expf(o0)-1.f);
        o0 = s[2]*inv + bias[col+2]; rA.z = o0>0.f? o0 : (__expf(o0)-1.f);
        o0 = s[3]*inv + bias[col+3]; rA.w = o0>0.f? o0 : (__expf(o0)-1.f);
        o0 = s[4]*inv + bias[col+4]; rB.x = o0>0.f? o0 : (__expf(o0)-1.f);
        o0 = s[5]*inv + bias[col+5]; rB.y = o0>0.f? o0 : (__expf(o0)-1.f);
        o0 = s[6]*inv + bias[col+6]; rB.z = o0>0.f? o0 : (__expf(o0)-1.f);
        o0 = s[7]*inv + bias[col+7]; rB.w = o0>0.f? o0 : (__expf(o0)-1.f);
        float4* dst = reinterpret_cast<float4*>(&d_h1[d*D1 + col]);
        dst[0] = rA; dst[1] = rB;
    }
}

// ---------------- GAT2 aggregation: warp per dst, 4 edges/iter ----------------
__global__ void k_gat2(const float* __restrict__ att, const float* __restrict__ bias,
                       float* __restrict__ out){
    int d = blockIdx.x*8 + (threadIdx.x>>5);
    int lane = threadIdx.x & 31;
    if (d >= NTOT) return;
    int g = lane >> 3, l8 = lane & 7;
    int col = l8*8;
    const float4* xr4 = reinterpret_cast<const float4*>(&d_xr2[d*OUTC + col]);
    float4 xrA = xr4[0], xrB = xr4[1];
    const float4* at4 = reinterpret_cast<const float4*>(&att[col]);
    float4 atA = at4[0], atB = at4[1];

    float den = 0.f;
    float s[8] = {0,0,0,0,0,0,0,0};
    int eb = d_off[d], ee = d_off[d+1];
    #pragma unroll 2
    for (int e0 = eb; e0 < ee; e0 += 4){
        int e = e0 + g;
        bool valid = (e < ee);
        int src = d_csr[valid ? e : eb];
        const float4* xl4 = reinterpret_cast<const float4*>(&d_xl2[src*OUTC + col]);
        float4 lA = xl4[0], lB = xl4[1];
        float t, q;
        t = lA.x + xrA.x; t = t>0.f? t : 0.2f*t; q  = atA.x*t;
        t = lA.y + xrA.y; t = t>0.f? t : 0.2f*t; q += atA.y*t;
        t = lA.z + xrA.z; t = t>0.f? t : 0.2f*t; q += atA.z*t;
        t = lA.w + xrA.w; t = t>0.f? t : 0.2f*t; q += atA.w*t;
        t = lB.x + xrB.x; t = t>0.f? t : 0.2f*t; q += atB.x*t;
        t = lB.y + xrB.y; t = t>0.f? t : 0.2f*t; q += atB.y*t;
        t = lB.z + xrB.z; t = t>0.f? t : 0.2f*t; q += atB.z*t;
        t = lB.w + xrB.w; t = t>0.f? t : 0.2f*t; q += atB.w*t;
        q += __shfl_xor_sync(0xffffffffu, q, 1);
        q += __shfl_xor_sync(0xffffffffu, q, 2);
        q += __shfl_xor_sync(0xffffffffu, q, 4);
        float wv = valid ? __expf(q) : 0.f;
        den += wv;
        s[0] += wv*lA.x; s[1] += wv*lA.y; s[2] += wv*lA.z; s[3] += wv*lA.w;
        s[4] += wv*lB.x; s[5] += wv*lB.y; s[6] += wv*lB.z; s[7] += wv*lB.w;
    }
    #pragma unroll
    for (int o=8;o<=16;o<<=1){
        den += __shfl_xor_sync(0xffffffffu, den, o);
        #pragma unroll
        for (int k=0;k<8;k++) s[k] += __shfl_xor_sync(0xffffffffu, s[k], o);
    }
    if (g == 0){
        float inv = __fdividef(1.f, den);
        float4 rA, rB;
        rA.x = s[0]*inv + bias[col+0];
        rA.y = s[1]*inv + bias[col+1];
        rA.z = s[2]*inv + bias[col+2];
        rA.w = s[3]*inv + bias[col+3];
        rB.x = s[4]*inv + bias[col+4];
        rB.y = s[5]*inv + bias[col+5];
        rB.z = s[6]*inv + bias[col+6];
        rB.w = s[7]*inv + bias[col+7];
        float4* dst = reinterpret_cast<float4*>(&out[d*OUTC + col]);
        dst[0] = rA; dst[1] = rB;
    }
}

// ---------------- host launch ----------------
extern "C" void kernel_launch(void* const* d_in, const int* in_sizes, int n_in,
                              void* d_out, int out_size){
    const int*   eib   = (const int*)d_in[0];
    const float* ve    = (const float*)d_in[1];
    const float* ac    = (const float*)d_in[2];
    const float* man   = (const float*)d_in[3];
    const float* mask  = (const float*)d_in[4];
    const float* c1w   = (const float*)d_in[6];
    const float* c1b   = (const float*)d_in[7];
    const float* bn1g  = (const float*)d_in[8];
    const float* bn1b  = (const float*)d_in[9];
    const float* c2w   = (const float*)d_in[10];
    const float* c2b   = (const float*)d_in[11];
    const float* bn2g  = (const float*)d_in[12];
    const float* bn2b  = (const float*)d_in[13];
    const float* gwih  = (const float*)d_in[14];
    const float* gwhh  = (const float*)d_in[15];
    const float* gbih  = (const float*)d_in[16];
    const float* gbhh  = (const float*)d_in[17];
    const float* g1wl  = (const float*)d_in[18];
    const float* g1bl  = (const float*)d_in[19];
    const float* g1wr  = (const float*)d_in[20];
    const float* g1br  = (const float*)d_in[21];
    const float* g1att = (const float*)d_in[22];
    const float* g1bias= (const float*)d_in[23];
    const float* g2wl  = (const float*)d_in[24];
    const float* g2bl  = (const float*)d_in[25];
    const float* g2wr  = (const float*)d_in[26];
    const float* g2br  = (const float*)d_in[27];
    const float* g2att = (const float*)d_in[28];
    const float* g2bias= (const float*)d_in[29];
    float* out = (float*)d_out;

    k_init<<<(NTOT+255)/256, 256>>>();
    k_conv1<<<(BB*POS+255)/256, 256>>>(man, ac, ve, c1w, c1b, bn1g, bn1b);
    k_conv2<<<dim3(BB, (POS+255)/256), 256>>>(c2w, c2b, bn2g, bn2b, gwih, gbih);
    k_man<<<(HN*NTOT+255)/256, 256>>>(man, mask);
    k_gru<<<(NTOT+63)/64, 64>>>(mask, gwhh, gbhh);
    k_hist<<<(ET+255)/256, 256>>>(eib);
    k_scan<<<1, 1024>>>();
    k_scatter<<<(ET+255)/256, 256>>>(eib);
    k_proj<<<dim3(2*D1/64, NTOT/64), 256>>>(1, g1wl, g1bl, g1wr, g1br);
    k_gat1<<<NTOT, 256>>>(g1att, g1bias);
    k_proj<<<dim3(2*OUTC/64, NTOT/64), 256>>>(2, g2wl, g2bl, g2wr, g2br);
    k_gat2<<<(NTOT+7)/8, 256>>>(g2att, g2bias, out);
}